// round 8
// baseline (speedup 1.0000x reference)
#include <cuda_runtime.h>
#include <cstdint>

#define L_SEQ  50
#define BATCH  256
#define DIN    256
#define LAT    512
#define HODE   1024
#define HID    1024
#define DSTRIDE 257
#define JC     3072
#define OUT2_OFF (L_SEQ*BATCH*LAT)

using u64 = unsigned long long;

// ---- persistent scratch ----
__device__ float g_S0[BATCH*LAT];
__device__ float g_S1[BATCH*LAT];
__device__ float g_Y [BATCH*LAT];
__device__ float g_P [4][BATCH*HODE];        // mlp1 raw split-K partials
__device__ float g_Q [8][BATCH*LAT];         // mlp2 split-K partials
__device__ float g_Gp[8][4][BATCH*HID];      // gru partials: r,z,nx,nh per K-slice
__device__ float g_WihT[DIN*JC];
__device__ float g_WhhT[HID*JC];

__device__ __forceinline__ u64 pack2(float a, float b){
    u64 r; asm("mov.b64 %0, {%1,%2};" : "=l"(r) : "f"(a), "f"(b)); return r;
}
__device__ __forceinline__ void unpack2(u64 v, float& a, float& b){
    asm("mov.b64 {%0,%1}, %2;" : "=f"(a), "=f"(b) : "l"(v));
}
__device__ __forceinline__ u64 fma2(u64 a, u64 b, u64 c){
    u64 d; asm("fma.rn.f32x2 %0, %1, %2, %3;" : "=l"(d) : "l"(a), "l"(b), "l"(c)); return d;
}
__device__ __forceinline__ ulonglong2 dup2(float x, float y){
    ulonglong2 v; v.x = pack2(x,x); v.y = pack2(y,y); return v;
}
__device__ __forceinline__ float fsigmoid(float x){ return 1.0f/(1.0f + __expf(-x)); }
__device__ __forceinline__ float ftanh(float x){ return 1.0f - 2.0f/(__expf(2.0f*x) + 1.0f); }

__global__ void k_zero(){
    int i = blockIdx.x*blockDim.x + threadIdx.x;
    if (i < BATCH*LAT) g_S0[i] = 0.0f;
}

// W[3072][K] -> WT[K][3072]
__global__ __launch_bounds__(256) void k_transpose(const float* __restrict__ W, int K,
                                                   float* __restrict__ WT)
{
    __shared__ float tile[32][33];
    const int j0 = blockIdx.x*32, k0 = blockIdx.y*32;
    const int r = threadIdx.x >> 3, c4 = (threadIdx.x & 7)*4;
    float4 v = *(const float4*)&W[(size_t)(j0+r)*K + k0 + c4];
    tile[r][c4+0]=v.x; tile[r][c4+1]=v.y; tile[r][c4+2]=v.z; tile[r][c4+3]=v.w;
    __syncthreads();
    float4 o = make_float4(tile[c4+0][r], tile[c4+1][r], tile[c4+2][r], tile[c4+3][r]);
    *(float4*)&WT[(size_t)(k0+r)*JC + j0 + c4] = o;
}

// ============ mlp1 partial: g_P[z] = A[:, z*128:(z+1)*128] @ W1[z*128:,:] ============
// BM=64, BN=64, BK=32, 256 thr, 4x4 thread tiles. grid (16,4,4)=256 blocks.
__global__ __launch_bounds__(256) void k_mlp1(const float* __restrict__ A,
                                              const float* __restrict__ W1)
{
    __shared__ __align__(16) u64   As[2][32][66];
    __shared__ __align__(16) float Bs[2][32][72];
    const int tid = threadIdx.x;
    const int tx = tid & 15, ty = tid >> 4;
    const int n0 = blockIdx.x*64, m0 = blockIdx.y*64, kb = blockIdx.z*128;
    const int ap = tid & 31, aq = (tid >> 5)*4;
    const int br = tid >> 3, bc = (tid & 7)*8;

    float4 ra, rb, wb0, wb1;
    u64 acc[4][2];
    #pragma unroll
    for (int r=0;r<4;r++){ acc[r][0]=0ULL; acc[r][1]=0ULL; }

    auto ldg = [&](int k0){
        const float* pa = &A[(size_t)(m0 + 2*ap)*LAT + kb + k0 + aq];
        ra = *(const float4*)pa; rb = *(const float4*)(pa + LAT);
        const float* pb = &W1[(size_t)(kb + k0 + br)*HODE + n0 + bc];
        wb0 = *(const float4*)pb; wb1 = *(const float4*)(pb+4);
    };
    auto sts = [&](int b){
        *(ulonglong2*)&As[b][aq+0][2*ap] = dup2(ra.x, rb.x);
        *(ulonglong2*)&As[b][aq+1][2*ap] = dup2(ra.y, rb.y);
        *(ulonglong2*)&As[b][aq+2][2*ap] = dup2(ra.z, rb.z);
        *(ulonglong2*)&As[b][aq+3][2*ap] = dup2(ra.w, rb.w);
        *(float4*)&Bs[b][br][bc] = wb0; *(float4*)&Bs[b][br][bc+4] = wb1;
    };

    ldg(0); sts(0); __syncthreads();
    for (int kt = 0; kt < 4; kt++){
        const int c = kt & 1;
        if (kt < 3) ldg((kt+1)*32);
        #pragma unroll
        for (int k = 0; k < 32; k++){
            ulonglong2 aA = *(const ulonglong2*)&As[c][k][ty*4];
            ulonglong2 aB = *(const ulonglong2*)&As[c][k][ty*4+2];
            ulonglong2 bb = *(const ulonglong2*)&Bs[c][k][tx*4];
            acc[0][0]=fma2(aA.x,bb.x,acc[0][0]); acc[0][1]=fma2(aA.x,bb.y,acc[0][1]);
            acc[1][0]=fma2(aA.y,bb.x,acc[1][0]); acc[1][1]=fma2(aA.y,bb.y,acc[1][1]);
            acc[2][0]=fma2(aB.x,bb.x,acc[2][0]); acc[2][1]=fma2(aB.x,bb.y,acc[2][1]);
            acc[3][0]=fma2(aB.y,bb.x,acc[3][0]); acc[3][1]=fma2(aB.y,bb.y,acc[3][1]);
        }
        if (kt < 3) sts(c^1);
        __syncthreads();
    }
    float* P = g_P[blockIdx.z];
    #pragma unroll
    for (int r = 0; r < 4; r++){
        const int m = m0 + ty*4 + r;
        #pragma unroll
        for (int p = 0; p < 2; p++)
            *(u64*)&P[(size_t)m*HODE + n0 + tx*4 + p*2] = acc[r][p];
    }
}

// ===== mlp2 partial: A = tanh(P0+P1+P2+P3+b1) fused in staging; g_Q[z] over K-slice =====
// grid (8,4,8)=256 blocks, K-slice 128.
__global__ __launch_bounds__(256) void k_mlp2(const float* __restrict__ W2,
                                              const float* __restrict__ b1)
{
    __shared__ __align__(16) u64   As[2][32][66];
    __shared__ __align__(16) float Bs[2][32][72];
    const int tid = threadIdx.x;
    const int tx = tid & 15, ty = tid >> 4;
    const int n0 = blockIdx.x*64, m0 = blockIdx.y*64, kb = blockIdx.z*128;
    const int ap = tid & 31, aq = (tid >> 5)*4;
    const int br = tid >> 3, bc = (tid & 7)*8;

    float4 ra, rb, wb0, wb1;
    u64 acc[4][2];
    #pragma unroll
    for (int r=0;r<4;r++){ acc[r][0]=0ULL; acc[r][1]=0ULL; }

    auto ldg = [&](int k0){
        const size_t off = (size_t)(m0 + 2*ap)*HODE + kb + k0 + aq;
        float4 c0 = *(const float4*)&b1[kb + k0 + aq];
        float4 a0 = *(const float4*)&g_P[0][off];
        float4 a1 = *(const float4*)&g_P[1][off];
        float4 a2 = *(const float4*)&g_P[2][off];
        float4 a3 = *(const float4*)&g_P[3][off];
        float4 d0 = *(const float4*)&g_P[0][off + HODE];
        float4 d1 = *(const float4*)&g_P[1][off + HODE];
        float4 d2 = *(const float4*)&g_P[2][off + HODE];
        float4 d3 = *(const float4*)&g_P[3][off + HODE];
        ra.x = ftanh(a0.x + a1.x + a2.x + a3.x + c0.x);
        ra.y = ftanh(a0.y + a1.y + a2.y + a3.y + c0.y);
        ra.z = ftanh(a0.z + a1.z + a2.z + a3.z + c0.z);
        ra.w = ftanh(a0.w + a1.w + a2.w + a3.w + c0.w);
        rb.x = ftanh(d0.x + d1.x + d2.x + d3.x + c0.x);
        rb.y = ftanh(d0.y + d1.y + d2.y + d3.y + c0.y);
        rb.z = ftanh(d0.z + d1.z + d2.z + d3.z + c0.z);
        rb.w = ftanh(d0.w + d1.w + d2.w + d3.w + c0.w);
        const float* pb = &W2[(size_t)(kb + k0 + br)*LAT + n0 + bc];
        wb0 = *(const float4*)pb; wb1 = *(const float4*)(pb+4);
    };
    auto sts = [&](int b){
        *(ulonglong2*)&As[b][aq+0][2*ap] = dup2(ra.x, rb.x);
        *(ulonglong2*)&As[b][aq+1][2*ap] = dup2(ra.y, rb.y);
        *(ulonglong2*)&As[b][aq+2][2*ap] = dup2(ra.z, rb.z);
        *(ulonglong2*)&As[b][aq+3][2*ap] = dup2(ra.w, rb.w);
        *(float4*)&Bs[b][br][bc] = wb0; *(float4*)&Bs[b][br][bc+4] = wb1;
    };

    ldg(0); sts(0); __syncthreads();
    for (int kt = 0; kt < 4; kt++){
        const int c = kt & 1;
        if (kt < 3) ldg((kt+1)*32);
        #pragma unroll
        for (int k = 0; k < 32; k++){
            ulonglong2 aA = *(const ulonglong2*)&As[c][k][ty*4];
            ulonglong2 aB = *(const ulonglong2*)&As[c][k][ty*4+2];
            ulonglong2 bb = *(const ulonglong2*)&Bs[c][k][tx*4];
            acc[0][0]=fma2(aA.x,bb.x,acc[0][0]); acc[0][1]=fma2(aA.x,bb.y,acc[0][1]);
            acc[1][0]=fma2(aA.y,bb.x,acc[1][0]); acc[1][1]=fma2(aA.y,bb.y,acc[1][1]);
            acc[2][0]=fma2(aB.x,bb.x,acc[2][0]); acc[2][1]=fma2(aB.x,bb.y,acc[2][1]);
            acc[3][0]=fma2(aB.y,bb.x,acc[3][0]); acc[3][1]=fma2(aB.y,bb.y,acc[3][1]);
        }
        if (kt < 3) sts(c^1);
        __syncthreads();
    }
    float* Q = g_Q[blockIdx.z];
    #pragma unroll
    for (int r = 0; r < 4; r++){
        const int m = m0 + ty*4 + r;
        #pragma unroll
        for (int p = 0; p < 2; p++)
            *(u64*)&Q[(size_t)m*LAT + n0 + tx*4 + p*2] = acc[r][p];
    }
}

// ===== Euler combine: Y = base + (sum Q + b2) * (dt/3) =====
__global__ __launch_bounds__(256) void k_euler(const float* __restrict__ base,
                                               const float* __restrict__ b2,
                                               const float* __restrict__ data, int t)
{
    const int e = (blockIdx.x*256 + threadIdx.x)*4;
    const int m = e / LAT, n = e % LAT;
    const float h = data[(size_t)(t*BATCH + m)*DSTRIDE + DIN] * (1.0f/3.0f);
    float4 b  = *(const float4*)&base[e];
    float4 c  = *(const float4*)&b2[n];
    float sx = c.x, sy = c.y, sz = c.z, sw = c.w;
    #pragma unroll
    for (int zz = 0; zz < 8; zz++){
        float4 q = *(const float4*)&g_Q[zz][e];
        sx += q.x; sy += q.y; sz += q.z; sw += q.w;
    }
    float4 o;
    o.x = b.x + sx*h; o.y = b.y + sy*h; o.z = b.z + sz*h; o.w = b.w + sw*h;
    *(float4*)&g_Y[e] = o;
}

// ===== GRU partials over virtual K = [x(256) | y(512) | s(512)], 8 slices of 160 =====
// BM=64 (batch), BN=64 (gate cols), 256 thr. grid (J/64, 4, 8).
__global__ __launch_bounds__(256) void k_gru(const float* __restrict__ data, int t,
                                             const float* __restrict__ Sread)
{
    __shared__ __align__(16) u64   As[2][32][66];
    __shared__ __align__(16) float Ws[2][3][32][72];
    const int tid = threadIdx.x;
    const int tx = tid & 15, ty = tid >> 4;
    const int j0 = blockIdx.x*64, i0 = blockIdx.y*64;
    const int z  = blockIdx.z;
    const int ap = tid & 31, aq = (tid >> 5)*4;
    const int br = tid >> 3, bc = (tid & 7)*8;

    float ra[4], rb[4];
    float4 w0a,w0b,w1a,w1b,w2a,w2b;
    u64 accr[4][2], accz[4][2], accx[4][2], acch[4][2];
    #pragma unroll
    for (int r=0;r<4;r++)
        #pragma unroll
        for (int p=0;p<2;p++){ accr[r][p]=0ULL; accz[r][p]=0ULL; accx[r][p]=0ULL; acch[r][p]=0ULL; }

    auto ldg = [&](int kt){
        const int kv = z*160 + kt*32;
        if (kv < 256){
            const float* p0 = &data[(size_t)(t*BATCH + i0 + 2*ap)*DSTRIDE + kv + aq];
            const float* p1 = p0 + DSTRIDE;
            #pragma unroll
            for (int q = 0; q < 4; q++){ ra[q] = p0[q]; rb[q] = p1[q]; }
        } else {
            const float* src = (kv < 768) ? g_Y : Sread;
            const int kc = (kv < 768) ? kv - 256 : kv - 768;
            const float* p = &src[(size_t)(i0 + 2*ap)*LAT + kc + aq];
            float4 v0 = *(const float4*)p, v1 = *(const float4*)(p + LAT);
            ra[0]=v0.x; ra[1]=v0.y; ra[2]=v0.z; ra[3]=v0.w;
            rb[0]=v1.x; rb[1]=v1.y; rb[2]=v1.z; rb[3]=v1.w;
        }
        const float* WT = (kv < 256) ? g_WihT : g_WhhT;
        const int kvw = (kv < 256) ? kv : kv - 256;
        const float* pw = &WT[(size_t)(kvw + br)*JC + j0 + bc];
        w0a = *(const float4*)pw;        w0b = *(const float4*)(pw+4);
        w1a = *(const float4*)(pw+1024); w1b = *(const float4*)(pw+1028);
        w2a = *(const float4*)(pw+2048); w2b = *(const float4*)(pw+2052);
    };
    auto sts = [&](int b){
        *(ulonglong2*)&As[b][aq+0][2*ap] = dup2(ra[0], rb[0]);
        *(ulonglong2*)&As[b][aq+1][2*ap] = dup2(ra[1], rb[1]);
        *(ulonglong2*)&As[b][aq+2][2*ap] = dup2(ra[2], rb[2]);
        *(ulonglong2*)&As[b][aq+3][2*ap] = dup2(ra[3], rb[3]);
        *(float4*)&Ws[b][0][br][bc] = w0a; *(float4*)&Ws[b][0][br][bc+4] = w0b;
        *(float4*)&Ws[b][1][br][bc] = w1a; *(float4*)&Ws[b][1][br][bc+4] = w1b;
        *(float4*)&Ws[b][2][br][bc] = w2a; *(float4*)&Ws[b][2][br][bc+4] = w2b;
    };

    ldg(0); sts(0); __syncthreads();
    for (int kt = 0; kt < 5; kt++){
        const int c = kt & 1;
        const bool isx = (z*160 + kt*32) < 256;
        if (kt < 4) ldg(kt+1);
        u64 (&an)[4][2] = isx ? accx : acch;
        #pragma unroll
        for (int k = 0; k < 32; k++){
            ulonglong2 aA = *(const ulonglong2*)&As[c][k][ty*4];
            ulonglong2 aB = *(const ulonglong2*)&As[c][k][ty*4+2];
            ulonglong2 br_= *(const ulonglong2*)&Ws[c][0][k][tx*4];
            ulonglong2 bz = *(const ulonglong2*)&Ws[c][1][k][tx*4];
            ulonglong2 bn_= *(const ulonglong2*)&Ws[c][2][k][tx*4];
            accr[0][0]=fma2(aA.x,br_.x,accr[0][0]); accr[0][1]=fma2(aA.x,br_.y,accr[0][1]);
            accr[1][0]=fma2(aA.y,br_.x,accr[1][0]); accr[1][1]=fma2(aA.y,br_.y,accr[1][1]);
            accr[2][0]=fma2(aB.x,br_.x,accr[2][0]); accr[2][1]=fma2(aB.x,br_.y,accr[2][1]);
            accr[3][0]=fma2(aB.y,br_.x,accr[3][0]); accr[3][1]=fma2(aB.y,br_.y,accr[3][1]);
            accz[0][0]=fma2(aA.x,bz.x,accz[0][0]); accz[0][1]=fma2(aA.x,bz.y,accz[0][1]);
            accz[1][0]=fma2(aA.y,bz.x,accz[1][0]); accz[1][1]=fma2(aA.y,bz.y,accz[1][1]);
            accz[2][0]=fma2(aB.x,bz.x,accz[2][0]); accz[2][1]=fma2(aB.x,bz.y,accz[2][1]);
            accz[3][0]=fma2(aB.y,bz.x,accz[3][0]); accz[3][1]=fma2(aB.y,bz.y,accz[3][1]);
            an[0][0]=fma2(aA.x,bn_.x,an[0][0]); an[0][1]=fma2(aA.x,bn_.y,an[0][1]);
            an[1][0]=fma2(aA.y,bn_.x,an[1][0]); an[1][1]=fma2(aA.y,bn_.y,an[1][1]);
            an[2][0]=fma2(aB.x,bn_.x,an[2][0]); an[2][1]=fma2(aB.x,bn_.y,an[2][1]);
            an[3][0]=fma2(aB.y,bn_.x,an[3][0]); an[3][1]=fma2(aB.y,bn_.y,an[3][1]);
        }
        if (kt < 4) sts(c^1);
        __syncthreads();
    }

    #pragma unroll
    for (int r = 0; r < 4; r++){
        const int i = i0 + ty*4 + r;
        #pragma unroll
        for (int p = 0; p < 2; p++){
            const size_t off = (size_t)i*HID + j0 + tx*4 + p*2;
            *(u64*)&g_Gp[z][0][off] = accr[r][p];
            *(u64*)&g_Gp[z][1][off] = accz[r][p];
            *(u64*)&g_Gp[z][2][off] = accx[r][p];
            *(u64*)&g_Gp[z][3][off] = acch[r][p];
        }
    }
}

// ===== GRU gate combine (8 partial slices) =====
__global__ __launch_bounds__(256) void k_gates(const float* __restrict__ bih,
                                               const float* __restrict__ bhh,
                                               const float* __restrict__ Sread,
                                               float* __restrict__ Swrite,
                                               float* __restrict__ out,
                                               int t, int J)
{
    const int e = (blockIdx.x*256 + threadIdx.x)*2;
    if (e >= BATCH*J) return;
    const int i = e / J, j = e % J;
    const size_t off = (size_t)i*HID + j;
    float rs0 = 0.f, rs1 = 0.f, zs0 = 0.f, zs1 = 0.f;
    float xs0 = 0.f, xs1 = 0.f, hs0 = 0.f, hs1 = 0.f;
    #pragma unroll
    for (int zz = 0; zz < 8; zz++){
        float2 rv = *(const float2*)&g_Gp[zz][0][off];
        float2 zv = *(const float2*)&g_Gp[zz][1][off];
        float2 xv = *(const float2*)&g_Gp[zz][2][off];
        float2 hv = *(const float2*)&g_Gp[zz][3][off];
        rs0 += rv.x; rs1 += rv.y;  zs0 += zv.x; zs1 += zv.y;
        xs0 += xv.x; xs1 += xv.y;  hs0 += hv.x; hs1 += hv.y;
    }
    const bool last = (t == L_SEQ-1);
    #pragma unroll
    for (int q = 0; q < 2; q++){
        const int jj = j + q;
        float rg = fsigmoid((q ? rs1 : rs0) + bih[jj] + bhh[jj]);
        float zg = fsigmoid((q ? zs1 : zs0) + bih[HID+jj] + bhh[HID+jj]);
        float ng = ftanh(((q ? xs1 : xs0) + bih[2*HID+jj]) + rg*((q ? hs1 : hs0) + bhh[2*HID+jj]));
        float hv = (jj < LAT) ? g_Y[(size_t)i*LAT + jj] : Sread[(size_t)i*LAT + jj - LAT];
        float v = (1.0f - zg)*ng + zg*hv;
        if (jj < LAT){
            out[(size_t)(t*BATCH + i)*LAT + jj] = v;
            Swrite[(size_t)i*LAT + jj] = v;
        }
        if (last) out[OUT2_OFF + (size_t)i*HID + jj] = v;
    }
}

extern "C" void kernel_launch(void* const* d_in, const int* in_sizes, int n_in,
                              void* d_out, int out_size)
{
    const float* data = (const float*)d_in[0];
    const float* w1   = (const float*)d_in[1];
    const float* b1   = (const float*)d_in[2];
    const float* w2   = (const float*)d_in[3];
    const float* b2   = (const float*)d_in[4];
    const float* wih  = (const float*)d_in[5];
    const float* bih  = (const float*)d_in[6];
    const float* whh  = (const float*)d_in[7];
    const float* bhh  = (const float*)d_in[8];
    float* out = (float*)d_out;

    float *S0, *S1;
    cudaGetSymbolAddress((void**)&S0, g_S0);
    cudaGetSymbolAddress((void**)&S1, g_S1);
    float *WihT, *WhhT;
    cudaGetSymbolAddress((void**)&WihT, g_WihT);
    cudaGetSymbolAddress((void**)&WhhT, g_WhhT);

    k_zero<<<(BATCH*LAT + 255)/256, 256>>>();
    k_transpose<<<dim3(JC/32, DIN/32), 256>>>(wih, DIN, WihT);
    k_transpose<<<dim3(JC/32, HID/32), 256>>>(whh, HID, WhhT);

    const dim3 g1(HODE/64, BATCH/64, 4);     // (16,4,4) = 256
    const dim3 g2(LAT/64,  BATCH/64, 8);     // (8,4,8)  = 256
    const dim3 ge(BATCH*LAT/4/256);          // 128

    for (int t = 0; t < L_SEQ; t++) {
        float* Sr = (t & 1) ? S1 : S0;
        float* Sw = (t & 1) ? S0 : S1;

        const float* base = Sr;
        for (int s = 0; s < 3; s++){
            k_mlp1<<<g1, 256>>>(base, w1);
            k_mlp2<<<g2, 256>>>(w2, b1);
            k_euler<<<ge, 256>>>(base, b2, data, t);
            base = (const float*)nullptr;           // set below
            float* Yp; cudaGetSymbolAddress((void**)&Yp, g_Y);
            base = Yp;
        }

        const int J = (t == L_SEQ-1) ? HID : LAT;
        dim3 g3(J/64, BATCH/64, 8);
        k_gru<<<g3, 256>>>(data, t, Sr);
        k_gates<<<(BATCH*J/2 + 255)/256, 256>>>(bih, bhh, Sr, Sw, out, t, J);
    }
    (void)in_sizes; (void)n_in; (void)out_size;
}

// round 9
// speedup vs baseline: 1.7440x; 1.7440x over previous
#include <cuda_runtime.h>
#include <cstdint>

#define L_SEQ  50
#define BATCH  256
#define DIN    256
#define LAT    512
#define HODE   1024
#define HID    1024
#define DSTRIDE 257
#define JC     3072
#define OUT2_OFF (L_SEQ*BATCH*LAT)

// ---- persistent scratch ----
__device__ float g_S0[BATCH*LAT];
__device__ float g_S1[BATCH*LAT];
__device__ float g_Y [BATCH*LAT];
__device__ float g_P [2][BATCH*HODE];     // mlp1 split-K partials (raw)
__device__ float g_Q [4][BATCH*LAT];      // mlp2 split-K partials (raw)
__device__ float g_Gp[3][BATCH*3072];     // gru partials per K-slice (x / y / s), gate-major
__device__ float g_W1c [LAT*HODE];        // tf32-rounded weights
__device__ float g_W2c [HODE*LAT];
__device__ float g_WihTc[DIN*JC];         // [k][g*1024+j], tf32-rounded
__device__ float g_WhhTc[HID*JC];

__device__ __forceinline__ float tf32r(float x){
    uint32_t u; asm("cvt.rna.tf32.f32 %0, %1;" : "=r"(u) : "f"(x));
    return __uint_as_float(u);
}
__device__ __forceinline__ float fsigmoid(float x){ return 1.0f/(1.0f + __expf(-x)); }
__device__ __forceinline__ float ftanh(float x){ return 1.0f - 2.0f/(__expf(2.0f*x) + 1.0f); }

__device__ __forceinline__ void mma8(float (&d)[4], const uint32_t (&a)[4], const uint32_t (&b)[2]){
    asm volatile("mma.sync.aligned.m16n8k8.row.col.f32.tf32.tf32.f32 "
        "{%0,%1,%2,%3}, {%4,%5,%6,%7}, {%8,%9}, {%0,%1,%2,%3};"
        : "+f"(d[0]),"+f"(d[1]),"+f"(d[2]),"+f"(d[3])
        : "r"(a[0]),"r"(a[1]),"r"(a[2]),"r"(a[3]), "r"(b[0]),"r"(b[1]));
}

// warp-tile compute over one 64x64x32 staged tile
__device__ __forceinline__ void mma_tile(const float (*As)[36], const float (*Bs)[72],
                                         int wm, int wn, int g, int t4, float (&d)[2][2][4])
{
    #pragma unroll
    for (int ks = 0; ks < 4; ks++){
        const int k8 = ks*8;
        uint32_t a[2][4], b[2][2];
        #pragma unroll
        for (int mi = 0; mi < 2; mi++){
            const int mr = wm*32 + mi*16 + g;
            a[mi][0] = __float_as_uint(As[mr  ][k8+t4  ]);
            a[mi][1] = __float_as_uint(As[mr+8][k8+t4  ]);
            a[mi][2] = __float_as_uint(As[mr  ][k8+t4+4]);
            a[mi][3] = __float_as_uint(As[mr+8][k8+t4+4]);
        }
        #pragma unroll
        for (int ni = 0; ni < 2; ni++){
            const int nc = wn*16 + ni*8 + g;
            b[ni][0] = __float_as_uint(Bs[k8+t4  ][nc]);
            b[ni][1] = __float_as_uint(Bs[k8+t4+4][nc]);
        }
        #pragma unroll
        for (int mi = 0; mi < 2; mi++)
            #pragma unroll
            for (int ni = 0; ni < 2; ni++)
                mma8(d[mi][ni], a[mi], b[ni]);
    }
}

__device__ __forceinline__ void epi_store(float* Out, int ld, int m0, int n0,
                                          int wm, int wn, int g, int t4, float (&d)[2][2][4])
{
    #pragma unroll
    for (int mi = 0; mi < 2; mi++){
        const int r0 = m0 + wm*32 + mi*16 + g;
        #pragma unroll
        for (int ni = 0; ni < 2; ni++){
            const int c = n0 + wn*16 + ni*8 + t4*2;
            *(float2*)&Out[(size_t)r0*ld + c]     = make_float2(d[mi][ni][0], d[mi][ni][1]);
            *(float2*)&Out[(size_t)(r0+8)*ld + c] = make_float2(d[mi][ni][2], d[mi][ni][3]);
        }
    }
}

__global__ void k_zero(){
    int i = blockIdx.x*blockDim.x + threadIdx.x;
    if (i < BATCH*LAT) g_S0[i] = 0.0f;
}

// elementwise tf32-round copy (float4)
__global__ __launch_bounds__(256) void k_cvt4(const float* __restrict__ in,
                                              float* __restrict__ out, int n4)
{
    int i = blockIdx.x*256 + threadIdx.x;
    if (i >= n4) return;
    float4 v = *(const float4*)&in[i*4];
    v.x = tf32r(v.x); v.y = tf32r(v.y); v.z = tf32r(v.z); v.w = tf32r(v.w);
    *(float4*)&out[i*4] = v;
}

// W[3072][K] -> WT[K][3072], tf32-rounded
__global__ __launch_bounds__(256) void k_transpose(const float* __restrict__ W, int K,
                                                   float* __restrict__ WT)
{
    __shared__ float tile[32][33];
    const int j0 = blockIdx.x*32, k0 = blockIdx.y*32;
    const int r = threadIdx.x >> 3, c4 = (threadIdx.x & 7)*4;
    float4 v = *(const float4*)&W[(size_t)(j0+r)*K + k0 + c4];
    tile[r][c4+0]=v.x; tile[r][c4+1]=v.y; tile[r][c4+2]=v.z; tile[r][c4+3]=v.w;
    __syncthreads();
    float4 o = make_float4(tf32r(tile[c4+0][r]), tf32r(tile[c4+1][r]),
                           tf32r(tile[c4+2][r]), tf32r(tile[c4+3][r]));
    *(float4*)&WT[(size_t)(k0+r)*JC + j0 + c4] = o;
}

// ======= mlp1 partial: g_P[z] = A[:, z*256:(z+1)*256] @ W1c[z*256:,:]  grid(16,4,2) =======
__global__ __launch_bounds__(256) void k_mlp1(const float* __restrict__ A)
{
    __shared__ float As[2][64][36];
    __shared__ float Bs[2][32][72];
    const int tid = threadIdx.x;
    const int lane = tid & 31, warp = tid >> 5;
    const int wm = warp >> 2, wn = warp & 3;
    const int g = lane >> 2, t4 = lane & 3;
    const int n0 = blockIdx.x*64, m0 = blockIdx.y*64, kb = blockIdx.z*256;
    const int am = tid >> 2, akq = (tid & 3)*8;
    const int bk = tid >> 3, bnq = (tid & 7)*8;

    float ra[8]; float4 rb0, rb1;
    float d[2][2][4];
    #pragma unroll
    for (int mi=0;mi<2;mi++) for (int ni=0;ni<2;ni++) for (int q=0;q<4;q++) d[mi][ni][q]=0.f;

    auto ldg = [&](int kt){
        const float* pa = &A[(size_t)(m0+am)*LAT + kb + kt*32 + akq];
        float4 v0 = *(const float4*)pa, v1 = *(const float4*)(pa+4);
        ra[0]=tf32r(v0.x); ra[1]=tf32r(v0.y); ra[2]=tf32r(v0.z); ra[3]=tf32r(v0.w);
        ra[4]=tf32r(v1.x); ra[5]=tf32r(v1.y); ra[6]=tf32r(v1.z); ra[7]=tf32r(v1.w);
        const float* pb = &g_W1c[(size_t)(kb + kt*32 + bk)*HODE + n0 + bnq];
        rb0 = *(const float4*)pb; rb1 = *(const float4*)(pb+4);
    };
    auto sts = [&](int b){
        *(float4*)&As[b][am][akq]   = make_float4(ra[0],ra[1],ra[2],ra[3]);
        *(float4*)&As[b][am][akq+4] = make_float4(ra[4],ra[5],ra[6],ra[7]);
        *(float4*)&Bs[b][bk][bnq] = rb0; *(float4*)&Bs[b][bk][bnq+4] = rb1;
    };

    ldg(0); sts(0); __syncthreads();
    for (int kt = 0; kt < 8; kt++){
        const int c = kt & 1;
        if (kt < 7) ldg(kt+1);
        mma_tile(As[c], Bs[c], wm, wn, g, t4, d);
        if (kt < 7) sts(c^1);
        __syncthreads();
    }
    epi_store(g_P[blockIdx.z], HODE, m0, n0, wm, wn, g, t4, d);
}

// ======= mlp2 partial: A' = tanh(P0+P1+b1) (fused in staging); grid(8,4,4) =======
__global__ __launch_bounds__(256) void k_mlp2(const float* __restrict__ b1)
{
    __shared__ float As[2][64][36];
    __shared__ float Bs[2][32][72];
    const int tid = threadIdx.x;
    const int lane = tid & 31, warp = tid >> 5;
    const int wm = warp >> 2, wn = warp & 3;
    const int g = lane >> 2, t4 = lane & 3;
    const int n0 = blockIdx.x*64, m0 = blockIdx.y*64, kb = blockIdx.z*256;
    const int am = tid >> 2, akq = (tid & 3)*8;
    const int bk = tid >> 3, bnq = (tid & 7)*8;

    float ra[8]; float4 rb0, rb1;
    float d[2][2][4];
    #pragma unroll
    for (int mi=0;mi<2;mi++) for (int ni=0;ni<2;ni++) for (int q=0;q<4;q++) d[mi][ni][q]=0.f;

    auto ldg = [&](int kt){
        const size_t off = (size_t)(m0+am)*HODE + kb + kt*32 + akq;
        float4 p0 = *(const float4*)&g_P[0][off];
        float4 p1 = *(const float4*)&g_P[1][off];
        float4 p2 = *(const float4*)&g_P[0][off+4];
        float4 p3 = *(const float4*)&g_P[1][off+4];
        float4 c0 = *(const float4*)&b1[kb + kt*32 + akq];
        float4 c1 = *(const float4*)&b1[kb + kt*32 + akq + 4];
        ra[0]=tf32r(ftanh(p0.x+p1.x+c0.x)); ra[1]=tf32r(ftanh(p0.y+p1.y+c0.y));
        ra[2]=tf32r(ftanh(p0.z+p1.z+c0.z)); ra[3]=tf32r(ftanh(p0.w+p1.w+c0.w));
        ra[4]=tf32r(ftanh(p2.x+p3.x+c1.x)); ra[5]=tf32r(ftanh(p2.y+p3.y+c1.y));
        ra[6]=tf32r(ftanh(p2.z+p3.z+c1.z)); ra[7]=tf32r(ftanh(p2.w+p3.w+c1.w));
        const float* pb = &g_W2c[(size_t)(kb + kt*32 + bk)*LAT + n0 + bnq];
        rb0 = *(const float4*)pb; rb1 = *(const float4*)(pb+4);
    };
    auto sts = [&](int b){
        *(float4*)&As[b][am][akq]   = make_float4(ra[0],ra[1],ra[2],ra[3]);
        *(float4*)&As[b][am][akq+4] = make_float4(ra[4],ra[5],ra[6],ra[7]);
        *(float4*)&Bs[b][bk][bnq] = rb0; *(float4*)&Bs[b][bk][bnq+4] = rb1;
    };

    ldg(0); sts(0); __syncthreads();
    for (int kt = 0; kt < 8; kt++){
        const int c = kt & 1;
        if (kt < 7) ldg(kt+1);
        mma_tile(As[c], Bs[c], wm, wn, g, t4, d);
        if (kt < 7) sts(c^1);
        __syncthreads();
    }
    epi_store(g_Q[blockIdx.z], LAT, m0, n0, wm, wn, g, t4, d);
}

// ======= Euler combine: Y = base + (Q0+Q1+Q2+Q3 + b2) * (dt/3) =======
__global__ __launch_bounds__(256) void k_euler(const float* __restrict__ base,
                                               const float* __restrict__ b2,
                                               const float* __restrict__ data, int t)
{
    const int e = (blockIdx.x*256 + threadIdx.x)*4;
    const int m = e / LAT, n = e % LAT;
    const float h = data[(size_t)(t*BATCH + m)*DSTRIDE + DIN] * (1.0f/3.0f);
    float4 b  = *(const float4*)&base[e];
    float4 c  = *(const float4*)&b2[n];
    float4 q0 = *(const float4*)&g_Q[0][e];
    float4 q1 = *(const float4*)&g_Q[1][e];
    float4 q2 = *(const float4*)&g_Q[2][e];
    float4 q3 = *(const float4*)&g_Q[3][e];
    float4 o;
    o.x = b.x + (q0.x+q1.x+q2.x+q3.x + c.x)*h;
    o.y = b.y + (q0.y+q1.y+q2.y+q3.y + c.y)*h;
    o.z = b.z + (q0.z+q1.z+q2.z+q3.z + c.z)*h;
    o.w = b.w + (q0.w+q1.w+q2.w+q3.w + c.w)*h;
    *(float4*)&g_Y[e] = o;
}

// ======= GRU gate-major GEMM: N' = 3*J compact cols; K-slices z: x(256)/y(512)/s(512) =======
// grid (3J/64, 4, 3)
__global__ __launch_bounds__(256) void k_gru(const float* __restrict__ data, int t,
                                             const float* __restrict__ Sread, int J)
{
    __shared__ float As[2][64][36];
    __shared__ float Bs[2][32][72];
    const int tid = threadIdx.x;
    const int lane = tid & 31, warp = tid >> 5;
    const int wm = warp >> 2, wn = warp & 3;
    const int g = lane >> 2, t4 = lane & 3;
    const int c0 = blockIdx.x*64, m0 = blockIdx.y*64;
    const int z = blockIdx.z;
    const int NC3 = 3*J;
    const int gate = c0 / J, j0 = c0 - gate*J;
    const int wcol = gate*1024 + j0;                 // column base in WT space
    const int KT = (z == 0) ? 8 : 16;
    const float* WT = (z == 0) ? g_WihTc : g_WhhTc;
    const int krow0 = (z == 2) ? 512 : 0;
    const int am = tid >> 2, akq = (tid & 3)*8;
    const int bk = tid >> 3, bnq = (tid & 7)*8;

    float ra[8]; float4 rb0, rb1;
    float d[2][2][4];
    #pragma unroll
    for (int mi=0;mi<2;mi++) for (int ni=0;ni<2;ni++) for (int q=0;q<4;q++) d[mi][ni][q]=0.f;

    auto ldg = [&](int kt){
        if (z == 0){
            const float* pa = &data[(size_t)(t*BATCH + m0 + am)*DSTRIDE + kt*32 + akq];
            #pragma unroll
            for (int q = 0; q < 8; q++) ra[q] = tf32r(pa[q]);
        } else {
            const float* src = (z == 1) ? g_Y : Sread;
            const float* pa = &src[(size_t)(m0+am)*LAT + kt*32 + akq];
            float4 v0 = *(const float4*)pa, v1 = *(const float4*)(pa+4);
            ra[0]=tf32r(v0.x); ra[1]=tf32r(v0.y); ra[2]=tf32r(v0.z); ra[3]=tf32r(v0.w);
            ra[4]=tf32r(v1.x); ra[5]=tf32r(v1.y); ra[6]=tf32r(v1.z); ra[7]=tf32r(v1.w);
        }
        const float* pb = &WT[(size_t)(krow0 + kt*32 + bk)*JC + wcol + bnq];
        rb0 = *(const float4*)pb; rb1 = *(const float4*)(pb+4);
    };
    auto sts = [&](int b){
        *(float4*)&As[b][am][akq]   = make_float4(ra[0],ra[1],ra[2],ra[3]);
        *(float4*)&As[b][am][akq+4] = make_float4(ra[4],ra[5],ra[6],ra[7]);
        *(float4*)&Bs[b][bk][bnq] = rb0; *(float4*)&Bs[b][bk][bnq+4] = rb1;
    };

    ldg(0); sts(0); __syncthreads();
    for (int kt = 0; kt < KT; kt++){
        const int c = kt & 1;
        if (kt < KT-1) ldg(kt+1);
        mma_tile(As[c], Bs[c], wm, wn, g, t4, d);
        if (kt < KT-1) sts(c^1);
        __syncthreads();
    }
    epi_store(g_Gp[z], NC3, m0, c0, wm, wn, g, t4, d);
}

// ======= GRU gate combine =======
__global__ __launch_bounds__(256) void k_gates(const float* __restrict__ bih,
                                               const float* __restrict__ bhh,
                                               const float* __restrict__ Sread,
                                               float* __restrict__ Swrite,
                                               float* __restrict__ out,
                                               int t, int J)
{
    const int e = (blockIdx.x*256 + threadIdx.x)*2;
    if (e >= BATCH*J) return;
    const int i = e / J, j = e - (e/J)*J;
    const int NC3 = 3*J;
    const size_t base = (size_t)i*NC3;
    float2 r0 = *(const float2*)&g_Gp[0][base + j];
    float2 r1 = *(const float2*)&g_Gp[1][base + j];
    float2 r2 = *(const float2*)&g_Gp[2][base + j];
    float2 z0 = *(const float2*)&g_Gp[0][base + J + j];
    float2 z1 = *(const float2*)&g_Gp[1][base + J + j];
    float2 z2 = *(const float2*)&g_Gp[2][base + J + j];
    float2 x0 = *(const float2*)&g_Gp[0][base + 2*J + j];
    float2 h1 = *(const float2*)&g_Gp[1][base + 2*J + j];
    float2 h2 = *(const float2*)&g_Gp[2][base + 2*J + j];
    const bool last = (t == L_SEQ-1);
    float rs[2] = { r0.x+r1.x+r2.x, r0.y+r1.y+r2.y };
    float zs[2] = { z0.x+z1.x+z2.x, z0.y+z1.y+z2.y };
    float xs[2] = { x0.x, x0.y };
    float hs[2] = { h1.x+h2.x, h1.y+h2.y };
    #pragma unroll
    for (int q = 0; q < 2; q++){
        const int jj = j + q;
        float rg = fsigmoid(rs[q] + bih[jj] + bhh[jj]);
        float zg = fsigmoid(zs[q] + bih[HID+jj] + bhh[HID+jj]);
        float ng = ftanh((xs[q] + bih[2*HID+jj]) + rg*(hs[q] + bhh[2*HID+jj]));
        float hv = (jj < LAT) ? g_Y[(size_t)i*LAT + jj]
                              : Sread[(size_t)i*LAT + jj - LAT];
        float v = (1.0f - zg)*ng + zg*hv;
        if (jj < LAT){
            out[(size_t)(t*BATCH + i)*LAT + jj] = v;
            Swrite[(size_t)i*LAT + jj] = v;
        }
        if (last) out[OUT2_OFF + (size_t)i*HID + jj] = v;
    }
}

extern "C" void kernel_launch(void* const* d_in, const int* in_sizes, int n_in,
                              void* d_out, int out_size)
{
    const float* data = (const float*)d_in[0];
    const float* w1   = (const float*)d_in[1];
    const float* b1   = (const float*)d_in[2];
    const float* w2   = (const float*)d_in[3];
    const float* b2   = (const float*)d_in[4];
    const float* wih  = (const float*)d_in[5];
    const float* bih  = (const float*)d_in[6];
    const float* whh  = (const float*)d_in[7];
    const float* bhh  = (const float*)d_in[8];
    float* out = (float*)d_out;

    float *S0, *S1, *W1c, *W2c, *WihT, *WhhT;
    cudaGetSymbolAddress((void**)&S0, g_S0);
    cudaGetSymbolAddress((void**)&S1, g_S1);
    cudaGetSymbolAddress((void**)&W1c, g_W1c);
    cudaGetSymbolAddress((void**)&W2c, g_W2c);
    cudaGetSymbolAddress((void**)&WihT, g_WihTc);
    cudaGetSymbolAddress((void**)&WhhT, g_WhhTc);

    k_zero<<<(BATCH*LAT + 255)/256, 256>>>();
    k_cvt4<<<(LAT*HODE/4 + 255)/256, 256>>>(w1, W1c, LAT*HODE/4);
    k_cvt4<<<(HODE*LAT/4 + 255)/256, 256>>>(w2, W2c, HODE*LAT/4);
    k_transpose<<<dim3(JC/32, DIN/32), 256>>>(wih, DIN, WihT);
    k_transpose<<<dim3(JC/32, HID/32), 256>>>(whh, HID, WhhT);

    const dim3 g1(HODE/64, BATCH/64, 2);     // (16,4,2) = 128
    const dim3 g2(LAT/64,  BATCH/64, 4);     // (8,4,4)  = 128
    const dim3 ge(BATCH*LAT/4/256);          // 128

    for (int t = 0; t < L_SEQ; t++) {
        float* Sr = (t & 1) ? S1 : S0;
        float* Sw = (t & 1) ? S0 : S1;
        float* Yp; cudaGetSymbolAddress((void**)&Yp, g_Y);

        const float* base = Sr;
        for (int s = 0; s < 3; s++){
            k_mlp1<<<g1, 256>>>(base);
            k_mlp2<<<g2, 256>>>(b1);
            k_euler<<<ge, 256>>>(base, b2, data, t);
            base = Yp;
        }

        const int J = (t == L_SEQ-1) ? HID : LAT;
        dim3 g3(3*J/64, BATCH/64, 3);
        k_gru<<<g3, 256>>>(data, t, Sr, J);
        k_gates<<<(BATCH*J/2 + 255)/256, 256>>>(bih, bhh, Sr, Sw, out, t, J);
    }
    (void)in_sizes; (void)n_in; (void)out_size;
}